// round 7
// baseline (speedup 1.0000x reference)
#include <cuda_runtime.h>
#include <cuda_bf16.h>
#include <cstdint>
#include <cstddef>

// ---------------------------------------------------------------------------
// HebbianTraceModule: B=8 H=8 S=4096 D=64 DM=768
// out(32768x768) = Qaddr(32768x512) @ M(512x768)
//   where M[h*64+p, m] = sum_q newT[h,p,q] * W_out[m, h*64+q]
//   newT = 0.99*(trace - G@trace) + 0.1*U
//   G = Qe^T Qe / denom,  U = Qs^T Vs / denom   (denom = 32752)
// ---------------------------------------------------------------------------

#define NROWS 32752   // B*(S-2)
#define SM1   4094    // S-2
#define DENOM 32752.0f

// scratch (device globals; zeroed every launch by k0)
__device__ float g_G[8 * 4096];
__device__ float g_U[8 * 4096];
__device__ float g_T[8 * 4096];
__device__ float g_M[512 * 768];

__device__ __forceinline__ uint32_t f2tf32(float f) {
    uint32_t u;
    asm("cvt.rna.tf32.f32 %0, %1;" : "=r"(u) : "f"(f));
    return u;
}

__device__ __forceinline__ void mma_tf32(float* c, const uint32_t* a, const uint32_t* b) {
    asm volatile(
        "mma.sync.aligned.m16n8k8.row.col.f32.tf32.tf32.f32 "
        "{%0,%1,%2,%3}, {%4,%5,%6,%7}, {%8,%9}, {%0,%1,%2,%3};\n"
        : "+f"(c[0]), "+f"(c[1]), "+f"(c[2]), "+f"(c[3])
        : "r"(a[0]), "r"(a[1]), "r"(a[2]), "r"(a[3]), "r"(b[0]), "r"(b[1]));
}

// cp.async 16B with zero-fill predicate: src_bytes==0 -> fill 16B of zeros.
__device__ __forceinline__ void cp_async16(uint32_t dst_smem, const void* src, int src_bytes) {
    asm volatile("cp.async.cg.shared.global [%0], [%1], 16, %2;\n"
                 :: "r"(dst_smem), "l"(src), "r"(src_bytes));
}
__device__ __forceinline__ void cp_commit() {
    asm volatile("cp.async.commit_group;\n");
}
template <int N>
__device__ __forceinline__ void cp_wait() {
    asm volatile("cp.async.wait_group %0;\n" :: "n"(N));
}

// ---------------------------------------------------------------------------
__global__ void k0_zero() {
    int i = blockIdx.x * blockDim.x + threadIdx.x;
    if (i < 8 * 4096) { g_G[i] = 0.0f; g_U[i] = 0.0f; }
}

// ---------------------------------------------------------------------------
// K1: per-head Gram reductions.
// grid (32 chunks, 8 heads), 256 threads. Each block: 1024 rows in 16 tiles of 64.
// Warps 0-3 accumulate G (normalized Q), warps 4-7 accumulate U (Q^T V).
// ---------------------------------------------------------------------------
__global__ __launch_bounds__(256) void k1_reduce(const float* __restrict__ Q,
                                                 const float* __restrict__ V) {
    __shared__ float sQ[64][72];   // pitch 72: 72%32=8 -> conflict-free frag loads
    __shared__ float sV[64][72];
    __shared__ float sInv[64];

    const int h    = blockIdx.y;
    const int tid  = threadIdx.x;
    const int warp = tid >> 5;
    const int lane = tid & 31;
    const int g    = lane >> 2;   // groupID
    const int t4   = lane & 3;    // threadID_in_group
    const bool isU = (warp >= 4);
    const int pbase = (warp & 3) * 16;

    float acc[8][4];
#pragma unroll
    for (int qt = 0; qt < 8; qt++)
#pragma unroll
        for (int i = 0; i < 4; i++) acc[qt][i] = 0.0f;

    for (int it = 0; it < 16; it++) {
        const int jbase = blockIdx.x * 1024 + it * 64;
        __syncthreads();
        // load 64 rows x 64 cols of Q_store and V_store
#pragma unroll
        for (int l = 0; l < 4; l++) {
            int idx = tid + l * 256;          // 0..1023 float4 slots
            int r   = idx >> 4;               // row 0..63
            int c4  = (idx & 15) << 2;        // col 0..60
            int j   = jbase + r;
            float4 q4 = make_float4(0.f, 0.f, 0.f, 0.f);
            float4 v4 = q4;
            if (j < NROWS) {
                int b  = j / SM1;
                int i2 = j - b * SM1;
                size_t base = ((size_t)(b * 8 + h) * 4096 + (size_t)i2) * 64 + c4;
                q4 = *(const float4*)(Q + base);
                v4 = *(const float4*)(V + base + 128);   // V[.., i2+2, ..]
            }
            *(float4*)&sQ[r][c4] = q4;
            *(float4*)&sV[r][c4] = v4;
        }
        __syncthreads();
        if (tid < 64) {
            float ssum = 0.0f;
#pragma unroll
            for (int c = 0; c < 64; c++) { float x = sQ[tid][c]; ssum += x * x; }
            sInv[tid] = 1.0f / fmaxf(sqrtf(ssum), 1e-8f);
        }
        __syncthreads();

#pragma unroll
        for (int kk = 0; kk < 8; kk++) {
            const int j0 = kk * 8 + t4;
            uint32_t a[4], bf[2];
            if (!isU) {
                const float inv0 = sInv[j0], inv1 = sInv[j0 + 4];
                a[0] = f2tf32(sQ[j0][pbase + g] * inv0);
                a[1] = f2tf32(sQ[j0][pbase + g + 8] * inv0);
                a[2] = f2tf32(sQ[j0 + 4][pbase + g] * inv1);
                a[3] = f2tf32(sQ[j0 + 4][pbase + g + 8] * inv1);
#pragma unroll
                for (int qt = 0; qt < 8; qt++) {
                    bf[0] = f2tf32(sQ[j0][qt * 8 + g] * inv0);
                    bf[1] = f2tf32(sQ[j0 + 4][qt * 8 + g] * inv1);
                    mma_tf32(acc[qt], a, bf);
                }
            } else {
                a[0] = f2tf32(sQ[j0][pbase + g]);
                a[1] = f2tf32(sQ[j0][pbase + g + 8]);
                a[2] = f2tf32(sQ[j0 + 4][pbase + g]);
                a[3] = f2tf32(sQ[j0 + 4][pbase + g + 8]);
#pragma unroll
                for (int qt = 0; qt < 8; qt++) {
                    bf[0] = f2tf32(sV[j0][qt * 8 + g]);
                    bf[1] = f2tf32(sV[j0 + 4][qt * 8 + g]);
                    mma_tf32(acc[qt], a, bf);
                }
            }
        }
    }

    float* dst = isU ? g_U : g_G;
    const int off = h * 4096;
#pragma unroll
    for (int qt = 0; qt < 8; qt++) {
        int row = pbase + g;
        int col = qt * 8 + 2 * t4;
        atomicAdd(&dst[off + row * 64 + col],           acc[qt][0]);
        atomicAdd(&dst[off + row * 64 + col + 1],       acc[qt][1]);
        atomicAdd(&dst[off + (row + 8) * 64 + col],     acc[qt][2]);
        atomicAdd(&dst[off + (row + 8) * 64 + col + 1], acc[qt][3]);
    }
}

// ---------------------------------------------------------------------------
// K2a: newT[h] = 0.99*(T - (G/denom)@T) + 0.1*(U/denom).  grid(8), 256 thr.
// ---------------------------------------------------------------------------
__global__ __launch_bounds__(256) void k2a_trace(const float* __restrict__ trace) {
    __shared__ float sT[64][68];
    const int h   = blockIdx.x;
    const int tid = threadIdx.x;
#pragma unroll
    for (int l = 0; l < 4; l++) {
        int idx = tid + l * 256;
        int r = idx >> 4, c4 = (idx & 15) << 2;
        *(float4*)&sT[r][c4] = *(const float4*)&trace[h * 4096 + r * 64 + c4];
    }
    __syncthreads();
    const int p  = tid >> 2;
    const int qg = (tid & 3) * 16;
    float accv[16];
#pragma unroll
    for (int j = 0; j < 16; j++) accv[j] = 0.0f;
    for (int r = 0; r < 64; r++) {
        float gg = g_G[h * 4096 + p * 64 + r];
#pragma unroll
        for (int j = 0; j < 16; j++) accv[j] += gg * sT[r][qg + j];
    }
    const float invden = 1.0f / DENOM;
#pragma unroll
    for (int j = 0; j < 16; j++) {
        float u   = g_U[h * 4096 + p * 64 + qg + j];
        float val = 0.99f * (sT[p][qg + j] - accv[j] * invden) + 0.1f * u * invden;
        g_T[h * 4096 + p * 64 + qg + j] = val;
    }
}

// ---------------------------------------------------------------------------
// K2b: g_M[h*64+p][m] = sum_q g_T[h][p][q] * W[m*512 + h*64 + q]
// grid (8 heads, 12 m-tiles of 64), 256 thr.
// ---------------------------------------------------------------------------
__global__ __launch_bounds__(256) void k2b_makeM(const float* __restrict__ W) {
    __shared__ float sT[64][68];
    __shared__ float sW[64][68];   // [m_local][q]
    const int h   = blockIdx.x;
    const int mt  = blockIdx.y;
    const int tid = threadIdx.x;
#pragma unroll
    for (int l = 0; l < 4; l++) {
        int idx = tid + l * 256;
        int r = idx >> 4, c4 = (idx & 15) << 2;
        *(float4*)&sT[r][c4] = *(const float4*)&g_T[h * 4096 + r * 64 + c4];
        *(float4*)&sW[r][c4] = *(const float4*)&W[(size_t)(mt * 64 + r) * 512 + h * 64 + c4];
    }
    __syncthreads();
    const int tp = tid & 15;   // p = tp*4 .. +3
    const int tm = tid >> 4;   // m = tm*4 .. +3
    float accb[4][4];
#pragma unroll
    for (int i = 0; i < 4; i++)
#pragma unroll
        for (int j = 0; j < 4; j++) accb[i][j] = 0.0f;
    for (int q = 0; q < 64; q++) {
        float tv[4], wv[4];
#pragma unroll
        for (int i = 0; i < 4; i++) tv[i] = sT[tp * 4 + i][q];
#pragma unroll
        for (int j = 0; j < 4; j++) wv[j] = sW[tm * 4 + j][q];
#pragma unroll
        for (int i = 0; i < 4; i++)
#pragma unroll
            for (int j = 0; j < 4; j++) accb[i][j] += tv[i] * wv[j];
    }
#pragma unroll
    for (int i = 0; i < 4; i++) {
        float4 v = make_float4(accb[i][0], accb[i][1], accb[i][2], accb[i][3]);
        *(float4*)&g_M[(size_t)(h * 64 + tp * 4 + i) * 768 + mt * 64 + tm * 4] = v;
    }
}

// ---------------------------------------------------------------------------
// K3: out(32768x768) = Qaddr(32768x512) @ g_M(512x768), tf32 mma.
// BM=128 BN=128 BK=32, grid (6, 256) — N-tile on x (fastest) so consecutive
// bids share the same 128-row A slab: per-wave A footprint ~13 MB -> L2-resident.
// 256 thr (8 warps, warp tile 64x32). Double-buffered cp.async pipeline
// (DYNAMIC smem: 70656 B > 48KB static cap).
// A[r, h*64+p] = (s==0) ? 0 : Q[b,h,s-1,p],  r = b*4096+s.
// ---------------------------------------------------------------------------
#define K3_SA_ELEMS (2 * 128 * 36)
#define K3_SB_ELEMS (2 * 32 * 132)
#define K3_SMEM_BYTES ((K3_SA_ELEMS + K3_SB_ELEMS) * 4)   // 70656

__global__ __launch_bounds__(256, 2) void k3_gemm(const float* __restrict__ Q,
                                                  float* __restrict__ out) {
    extern __shared__ float dsm[];
    float (*sA)[128][36] = reinterpret_cast<float (*)[128][36]>(dsm);            // pitch 36 (%32=4)
    float (*sB)[32][132] = reinterpret_cast<float (*)[32][132]>(dsm + K3_SA_ELEMS); // pitch 132

    const int tid  = threadIdx.x;
    const int warp = tid >> 5;
    const int lane = tid & 31;
    const int g    = lane >> 2;
    const int t4   = lane & 3;

    const int rbase = blockIdx.y * 128;  // row-tile (slow axis)
    const int nbase = blockIdx.x * 128;  // N-tile (fast axis -> L2 A reuse)
    const int b     = rbase >> 12;       // whole block within one b (128 | 4096)
    const int s0    = rbase & 4095;
    const int wm    = (warp >> 2) * 64;  // 0 or 64
    const int wn    = (warp & 3) * 32;

    // per-thread load coordinates (fixed across tiles)
    const int ar   = tid >> 1;           // A row 0..127 (2 threads per row)
    const int acb  = (tid & 1) * 16;     // A col half: 0..15 or 16..31 (4 x 16B each)
    const int br   = tid >> 3;           // B row 0..31
    const int bc4  = (tid & 7) << 2;     // B col base (+32 stride below)
    const int s_a  = s0 + ar;
    const int s_src  = (s_a > 0) ? (s_a - 1) : 0;   // clamp: keep src address in-bounds
    const int abytes = (s_a > 0) ? 16 : 0;          // 0 -> cp.async zero-fills

    float acc[4][4][4];
#pragma unroll
    for (int mt = 0; mt < 4; mt++)
#pragma unroll
        for (int nt = 0; nt < 4; nt++)
#pragma unroll
            for (int i = 0; i < 4; i++) acc[mt][nt][i] = 0.0f;

    // issue loads for k-tile `kt` into buffer `buf`
    auto issue_tile = [&](int kt, int buf) {
        const int kbase = kt * 32;
        const int hh = kbase >> 6;
        const int p0 = kbase & 63;
        // A tile: 128 x 32. 256 thr x 4 x 16B = 16384 B = full tile.
        const float* aptr = Q + ((size_t)(b * 8 + hh) * 4096 + (size_t)s_src) * 64 + p0;
#pragma unroll
        for (int l = 0; l < 4; l++) {
            int c = acb + l * 4;        // cols {0,4,8,12} or {16,20,24,28}
            cp_async16((uint32_t)__cvta_generic_to_shared(&sA[buf][ar][c]), aptr + c, abytes);
        }
        // B tile: 32 x 128. 256 thr x 4 x 16B = 16384 B = full tile.
        const float* bptr = &g_M[(size_t)(kbase + br) * 768 + nbase];
#pragma unroll
        for (int l = 0; l < 4; l++) {
            int c = bc4 + l * 32;
            cp_async16((uint32_t)__cvta_generic_to_shared(&sB[buf][br][c]), bptr + c, 16);
        }
        cp_commit();
    };

    issue_tile(0, 0);

    for (int kt = 0; kt < 16; kt++) {
        const int cur = kt & 1;
        if (kt < 15) { issue_tile(kt + 1, cur ^ 1); cp_wait<1>(); }
        else         { cp_wait<0>(); }
        __syncthreads();

#pragma unroll
        for (int kk = 0; kk < 4; kk++) {
            const int k0 = kk * 8 + t4;
            uint32_t a[4][4], bb[4][2];
#pragma unroll
            for (int mt = 0; mt < 4; mt++) {
                int m0 = wm + mt * 16 + g;
                a[mt][0] = f2tf32(sA[cur][m0][k0]);
                a[mt][1] = f2tf32(sA[cur][m0 + 8][k0]);
                a[mt][2] = f2tf32(sA[cur][m0][k0 + 4]);
                a[mt][3] = f2tf32(sA[cur][m0 + 8][k0 + 4]);
            }
#pragma unroll
            for (int nt = 0; nt < 4; nt++) {
                int n0 = wn + nt * 8 + g;
                bb[nt][0] = f2tf32(sB[cur][k0][n0]);
                bb[nt][1] = f2tf32(sB[cur][k0 + 4][n0]);
            }
#pragma unroll
            for (int mt = 0; mt < 4; mt++)
#pragma unroll
                for (int nt = 0; nt < 4; nt++)
                    mma_tf32(acc[mt][nt], a[mt], bb[nt]);
        }
        __syncthreads();   // protect buffer `cur` before it is refilled next iter
    }

    // epilogue: float2 stores (c0,c1 adjacent cols)
#pragma unroll
    for (int mt = 0; mt < 4; mt++) {
#pragma unroll
        for (int nt = 0; nt < 4; nt++) {
            int r = rbase + wm + mt * 16 + g;
            int c = nbase + wn + nt * 8 + 2 * t4;
            float2 v0 = make_float2(acc[mt][nt][0], acc[mt][nt][1]);
            float2 v1 = make_float2(acc[mt][nt][2], acc[mt][nt][3]);
            *(float2*)&out[(size_t)r * 768 + c]       = v0;
            *(float2*)&out[(size_t)(r + 8) * 768 + c] = v1;
        }
    }
}

// ---------------------------------------------------------------------------
extern "C" void kernel_launch(void* const* d_in, const int* in_sizes, int n_in,
                              void* d_out, int out_size) {
    const float* Q     = (const float*)d_in[0];
    const float* V     = (const float*)d_in[1];
    const float* trace = (const float*)d_in[2];
    const float* W     = (const float*)d_in[3];
    float* out = (float*)d_out;

    // dynamic-smem opt-in for K3 (host attribute set; idempotent, capture-safe)
    cudaFuncSetAttribute(k3_gemm, cudaFuncAttributeMaxDynamicSharedMemorySize,
                         K3_SMEM_BYTES);

    k0_zero<<<128, 256>>>();
    k1_reduce<<<dim3(32, 8), 256>>>(Q, V);
    k2a_trace<<<8, 256>>>(trace);
    k2b_makeM<<<dim3(8, 12), 256>>>(W);
    k3_gemm<<<dim3(6, 256), 256, K3_SMEM_BYTES>>>(Q, out);
}

// round 11
// speedup vs baseline: 1.0170x; 1.0170x over previous
#include <cuda_runtime.h>
#include <cuda_bf16.h>
#include <cuda_fp16.h>
#include <cstdint>
#include <cstddef>

// ---------------------------------------------------------------------------
// HebbianTraceModule: B=8 H=8 S=4096 D=64 DM=768
// out(32768x768) = Qaddr(32768x512) @ M(512x768)
//   M[h*64+p, m] = sum_q newT[h,p,q] * W_out[m, h*64+q]
//   newT = 0.99*(trace - G@trace) + 0.1*U;  G = Qe^T Qe/den, U = Qs^T Vs/den
// NOTE: harness PTX target is compute_103 (no 'a') -> tcgen05 unavailable.
// K3 uses mma.sync.m16n8k16.f16 (same 10-bit mantissa as tf32, half the mmas).
// ---------------------------------------------------------------------------

#define NROWS 32752
#define SM1   4094
#define DENOM 32752.0f

__device__ float g_G[8 * 4096];
__device__ float g_U[8 * 4096];
__device__ float g_T[8 * 4096];
__device__ float g_M[512 * 768];

__device__ __forceinline__ uint32_t f2tf32(float f) {
    uint32_t u;
    asm("cvt.rna.tf32.f32 %0, %1;" : "=r"(u) : "f"(f));
    return u;
}

// pack two f32 -> f16x2 (lo = first arg, hi = second arg)
__device__ __forceinline__ uint32_t f2h2(float lo, float hi) {
    uint32_t u;
    asm("cvt.rn.f16x2.f32 %0, %1, %2;" : "=r"(u) : "f"(hi), "f"(lo));
    return u;
}

__device__ __forceinline__ void mma_tf32(float* c, const uint32_t* a, const uint32_t* b) {
    asm volatile(
        "mma.sync.aligned.m16n8k8.row.col.f32.tf32.tf32.f32 "
        "{%0,%1,%2,%3}, {%4,%5,%6,%7}, {%8,%9}, {%0,%1,%2,%3};\n"
        : "+f"(c[0]), "+f"(c[1]), "+f"(c[2]), "+f"(c[3])
        : "r"(a[0]), "r"(a[1]), "r"(a[2]), "r"(a[3]), "r"(b[0]), "r"(b[1]));
}

__device__ __forceinline__ void mma_f16(float* c, const uint32_t* a, const uint32_t* b) {
    asm volatile(
        "mma.sync.aligned.m16n8k16.row.col.f32.f16.f16.f32 "
        "{%0,%1,%2,%3}, {%4,%5,%6,%7}, {%8,%9}, {%0,%1,%2,%3};\n"
        : "+f"(c[0]), "+f"(c[1]), "+f"(c[2]), "+f"(c[3])
        : "r"(a[0]), "r"(a[1]), "r"(a[2]), "r"(a[3]), "r"(b[0]), "r"(b[1]));
}

__device__ __forceinline__ void cp_async16(uint32_t dst_smem, const void* src, int src_bytes) {
    asm volatile("cp.async.cg.shared.global [%0], [%1], 16, %2;\n"
                 :: "r"(dst_smem), "l"(src), "r"(src_bytes));
}
__device__ __forceinline__ void cp_commit() { asm volatile("cp.async.commit_group;\n"); }
template <int N>
__device__ __forceinline__ void cp_wait() { asm volatile("cp.async.wait_group %0;\n" :: "n"(N)); }

// ---------------------------------------------------------------------------
__global__ void k0_zero() {
    int i = blockIdx.x * blockDim.x + threadIdx.x;
    if (i < 8 * 4096) { g_G[i] = 0.0f; g_U[i] = 0.0f; }
}

// ---------------------------------------------------------------------------
// K1: per-head Gram reductions (unchanged from the 346us baseline).
// ---------------------------------------------------------------------------
__global__ __launch_bounds__(256) void k1_reduce(const float* __restrict__ Q,
                                                 const float* __restrict__ V) {
    __shared__ float sQ[64][72];
    __shared__ float sV[64][72];
    __shared__ float sInv[64];

    const int h    = blockIdx.y;
    const int tid  = threadIdx.x;
    const int warp = tid >> 5;
    const int lane = tid & 31;
    const int g    = lane >> 2;
    const int t4   = lane & 3;
    const bool isU = (warp >= 4);
    const int pbase = (warp & 3) * 16;

    float acc[8][4];
#pragma unroll
    for (int qt = 0; qt < 8; qt++)
#pragma unroll
        for (int i = 0; i < 4; i++) acc[qt][i] = 0.0f;

    for (int it = 0; it < 16; it++) {
        const int jbase = blockIdx.x * 1024 + it * 64;
        __syncthreads();
#pragma unroll
        for (int l = 0; l < 4; l++) {
            int idx = tid + l * 256;
            int r   = idx >> 4;
            int c4  = (idx & 15) << 2;
            int j   = jbase + r;
            float4 q4 = make_float4(0.f, 0.f, 0.f, 0.f);
            float4 v4 = q4;
            if (j < NROWS) {
                int b  = j / SM1;
                int i2 = j - b * SM1;
                size_t base = ((size_t)(b * 8 + h) * 4096 + (size_t)i2) * 64 + c4;
                q4 = *(const float4*)(Q + base);
                v4 = *(const float4*)(V + base + 128);
            }
            *(float4*)&sQ[r][c4] = q4;
            *(float4*)&sV[r][c4] = v4;
        }
        __syncthreads();
        if (tid < 64) {
            float ssum = 0.0f;
#pragma unroll
            for (int c = 0; c < 64; c++) { float x = sQ[tid][c]; ssum += x * x; }
            sInv[tid] = 1.0f / fmaxf(sqrtf(ssum), 1e-8f);
        }
        __syncthreads();

#pragma unroll
        for (int kk = 0; kk < 8; kk++) {
            const int j0 = kk * 8 + t4;
            uint32_t a[4], bf[2];
            if (!isU) {
                const float inv0 = sInv[j0], inv1 = sInv[j0 + 4];
                a[0] = f2tf32(sQ[j0][pbase + g] * inv0);
                a[1] = f2tf32(sQ[j0][pbase + g + 8] * inv0);
                a[2] = f2tf32(sQ[j0 + 4][pbase + g] * inv1);
                a[3] = f2tf32(sQ[j0 + 4][pbase + g + 8] * inv1);
#pragma unroll
                for (int qt = 0; qt < 8; qt++) {
                    bf[0] = f2tf32(sQ[j0][qt * 8 + g] * inv0);
                    bf[1] = f2tf32(sQ[j0 + 4][qt * 8 + g] * inv1);
                    mma_tf32(acc[qt], a, bf);
                }
            } else {
                a[0] = f2tf32(sQ[j0][pbase + g]);
                a[1] = f2tf32(sQ[j0][pbase + g + 8]);
                a[2] = f2tf32(sQ[j0 + 4][pbase + g]);
                a[3] = f2tf32(sQ[j0 + 4][pbase + g + 8]);
#pragma unroll
                for (int qt = 0; qt < 8; qt++) {
                    bf[0] = f2tf32(sV[j0][qt * 8 + g]);
                    bf[1] = f2tf32(sV[j0 + 4][qt * 8 + g]);
                    mma_tf32(acc[qt], a, bf);
                }
            }
        }
    }

    float* dst = isU ? g_U : g_G;
    const int off = h * 4096;
#pragma unroll
    for (int qt = 0; qt < 8; qt++) {
        int row = pbase + g;
        int col = qt * 8 + 2 * t4;
        atomicAdd(&dst[off + row * 64 + col],           acc[qt][0]);
        atomicAdd(&dst[off + row * 64 + col + 1],       acc[qt][1]);
        atomicAdd(&dst[off + (row + 8) * 64 + col],     acc[qt][2]);
        atomicAdd(&dst[off + (row + 8) * 64 + col + 1], acc[qt][3]);
    }
}

// ---------------------------------------------------------------------------
// K2a (unchanged)
// ---------------------------------------------------------------------------
__global__ __launch_bounds__(256) void k2a_trace(const float* __restrict__ trace) {
    __shared__ float sT[64][68];
    const int h   = blockIdx.x;
    const int tid = threadIdx.x;
#pragma unroll
    for (int l = 0; l < 4; l++) {
        int idx = tid + l * 256;
        int r = idx >> 4, c4 = (idx & 15) << 2;
        *(float4*)&sT[r][c4] = *(const float4*)&trace[h * 4096 + r * 64 + c4];
    }
    __syncthreads();
    const int p  = tid >> 2;
    const int qg = (tid & 3) * 16;
    float accv[16];
#pragma unroll
    for (int j = 0; j < 16; j++) accv[j] = 0.0f;
    for (int r = 0; r < 64; r++) {
        float gg = g_G[h * 4096 + p * 64 + r];
#pragma unroll
        for (int j = 0; j < 16; j++) accv[j] += gg * sT[r][qg + j];
    }
    const float invden = 1.0f / DENOM;
#pragma unroll
    for (int j = 0; j < 16; j++) {
        float u   = g_U[h * 4096 + p * 64 + qg + j];
        float val = 0.99f * (sT[p][qg + j] - accv[j] * invden) + 0.1f * u * invden;
        g_T[h * 4096 + p * 64 + qg + j] = val;
    }
}

// ---------------------------------------------------------------------------
// K2b (unchanged: writes g_M[hp][m])
// ---------------------------------------------------------------------------
__global__ __launch_bounds__(256) void k2b_makeM(const float* __restrict__ W) {
    __shared__ float sT[64][68];
    __shared__ float sW[64][68];
    const int h   = blockIdx.x;
    const int mt  = blockIdx.y;
    const int tid = threadIdx.x;
#pragma unroll
    for (int l = 0; l < 4; l++) {
        int idx = tid + l * 256;
        int r = idx >> 4, c4 = (idx & 15) << 2;
        *(float4*)&sT[r][c4] = *(const float4*)&g_T[h * 4096 + r * 64 + c4];
        *(float4*)&sW[r][c4] = *(const float4*)&W[(size_t)(mt * 64 + r) * 512 + h * 64 + c4];
    }
    __syncthreads();
    const int tp = tid & 15;
    const int tm = tid >> 4;
    float accb[4][4];
#pragma unroll
    for (int i = 0; i < 4; i++)
#pragma unroll
        for (int j = 0; j < 4; j++) accb[i][j] = 0.0f;
    for (int q = 0; q < 64; q++) {
        float tv[4], wv[4];
#pragma unroll
        for (int i = 0; i < 4; i++) tv[i] = sT[tp * 4 + i][q];
#pragma unroll
        for (int j = 0; j < 4; j++) wv[j] = sW[tm * 4 + j][q];
#pragma unroll
        for (int i = 0; i < 4; i++)
#pragma unroll
            for (int j = 0; j < 4; j++) accb[i][j] += tv[i] * wv[j];
    }
#pragma unroll
    for (int i = 0; i < 4; i++) {
        float4 v = make_float4(accb[i][0], accb[i][1], accb[i][2], accb[i][3]);
        *(float4*)&g_M[(size_t)(h * 64 + tp * 4 + i) * 768 + mt * 64 + tm * 4] = v;
    }
}

// ---------------------------------------------------------------------------
// K3: out(32768x768) = Qaddr(32768x512) @ g_M(512x768), fp16 mma (m16n8k16).
// BM=128 BN=128 BK=32, grid (6, 256) — N-tile fastest (L2 A reuse).
// Double-buffered cp.async. DYNAMIC smem (70656 B).
// A[r, h*64+p] = (s==0) ? 0 : Q[b,h,s-1,p],  r = b*4096+s.
// ---------------------------------------------------------------------------
#define K3_SA_ELEMS (2 * 128 * 36)
#define K3_SB_ELEMS (2 * 32 * 132)
#define K3_SMEM_BYTES ((K3_SA_ELEMS + K3_SB_ELEMS) * 4)   // 70656

__global__ __launch_bounds__(256, 2) void k3_gemm(const float* __restrict__ Q,
                                                  float* __restrict__ out) {
    extern __shared__ float dsm[];
    float (*sA)[128][36] = reinterpret_cast<float (*)[128][36]>(dsm);
    float (*sB)[32][132] = reinterpret_cast<float (*)[32][132]>(dsm + K3_SA_ELEMS);

    const int tid  = threadIdx.x;
    const int warp = tid >> 5;
    const int lane = tid & 31;
    const int g    = lane >> 2;
    const int t4   = lane & 3;

    const int rbase = blockIdx.y * 128;  // row-tile (slow axis)
    const int nbase = blockIdx.x * 128;  // N-tile (fast axis)
    const int b     = rbase >> 12;
    const int s0    = rbase & 4095;
    const int wm    = (warp >> 2) * 64;
    const int wn    = (warp & 3) * 32;

    const int ar   = tid >> 1;
    const int acb  = (tid & 1) * 16;
    const int br   = tid >> 3;
    const int bc4  = (tid & 7) << 2;
    const int s_a  = s0 + ar;
    const int s_src  = (s_a > 0) ? (s_a - 1) : 0;
    const int abytes = (s_a > 0) ? 16 : 0;

    float acc[4][4][4];
#pragma unroll
    for (int mt = 0; mt < 4; mt++)
#pragma unroll
        for (int nt = 0; nt < 4; nt++)
#pragma unroll
            for (int i = 0; i < 4; i++) acc[mt][nt][i] = 0.0f;

    auto issue_tile = [&](int kt, int buf) {
        const int kbase = kt * 32;
        const int hh = kbase >> 6;
        const int p0 = kbase & 63;
        const float* aptr = Q + ((size_t)(b * 8 + hh) * 4096 + (size_t)s_src) * 64 + p0;
#pragma unroll
        for (int l = 0; l < 4; l++) {
            int c = acb + l * 4;
            cp_async16((uint32_t)__cvta_generic_to_shared(&sA[buf][ar][c]), aptr + c, abytes);
        }
        const float* bptr = &g_M[(size_t)(kbase + br) * 768 + nbase];
#pragma unroll
        for (int l = 0; l < 4; l++) {
            int c = bc4 + l * 32;
            cp_async16((uint32_t)__cvta_generic_to_shared(&sB[buf][br][c]), bptr + c, 16);
        }
        cp_commit();
    };

    issue_tile(0, 0);

    for (int kt = 0; kt < 16; kt++) {
        const int cur = kt & 1;
        if (kt < 15) { issue_tile(kt + 1, cur ^ 1); cp_wait<1>(); }
        else         { cp_wait<0>(); }
        __syncthreads();

        // fp16 m16n8k16: 2 K-steps of 16 per 32-wide tile
#pragma unroll
        for (int kk2 = 0; kk2 < 2; kk2++) {
            const int k0 = kk2 * 16 + 2 * t4;   // even -> float2-aligned
            uint32_t a[4][4], bb[4][2];
#pragma unroll
            for (int mt = 0; mt < 4; mt++) {
                int m0 = wm + mt * 16 + g;
                float2 p00 = *(const float2*)&sA[cur][m0][k0];
                float2 p10 = *(const float2*)&sA[cur][m0 + 8][k0];
                float2 p01 = *(const float2*)&sA[cur][m0][k0 + 8];
                float2 p11 = *(const float2*)&sA[cur][m0 + 8][k0 + 8];
                a[mt][0] = f2h2(p00.x, p00.y);
                a[mt][1] = f2h2(p10.x, p10.y);
                a[mt][2] = f2h2(p01.x, p01.y);
                a[mt][3] = f2h2(p11.x, p11.y);
            }
#pragma unroll
            for (int nt = 0; nt < 4; nt++) {
                int n0 = wn + nt * 8 + g;
                bb[nt][0] = f2h2(sB[cur][k0][n0],     sB[cur][k0 + 1][n0]);
                bb[nt][1] = f2h2(sB[cur][k0 + 8][n0], sB[cur][k0 + 9][n0]);
            }
#pragma unroll
            for (int mt = 0; mt < 4; mt++)
#pragma unroll
                for (int nt = 0; nt < 4; nt++)
                    mma_f16(acc[mt][nt], a[mt], bb[nt]);
        }
        __syncthreads();
    }

    // epilogue: float2 stores (c0,c1 adjacent cols) — C layout identical to k8
#pragma unroll
    for (int mt = 0; mt < 4; mt++) {
#pragma unroll
        for (int nt = 0; nt < 4; nt++) {
            int r = rbase + wm + mt * 16 + g;
            int c = nbase + wn + nt * 8 + 2 * t4;
            float2 v0 = make_float2(acc[mt][nt][0], acc[mt][nt][1]);
            float2 v1 = make_float2(acc[mt][nt][2], acc[mt][nt][3]);
            *(float2*)&out[(size_t)r * 768 + c]       = v0;
            *(float2*)&out[(size_t)(r + 8) * 768 + c] = v1;
        }
    }
}

// ---------------------------------------------------------------------------
extern "C" void kernel_launch(void* const* d_in, const int* in_sizes, int n_in,
                              void* d_out, int out_size) {
    const float* Q     = (const float*)d_in[0];
    const float* V     = (const float*)d_in[1];
    const float* trace = (const float*)d_in[2];
    const float* W     = (const float*)d_in[3];
    float* out = (float*)d_out;

    cudaFuncSetAttribute(k3_gemm, cudaFuncAttributeMaxDynamicSharedMemorySize,
                         K3_SMEM_BYTES);

    k0_zero<<<128, 256>>>();
    k1_reduce<<<dim3(32, 8), 256>>>(Q, V);
    k2a_trace<<<8, 256>>>(trace);
    k2b_makeM<<<dim3(8, 12), 256>>>(W);
    k3_gemm<<<dim3(6, 256), 256, K3_SMEM_BYTES>>>(Q, out);
}